// round 12
// baseline (speedup 1.0000x reference)
#include <cuda_runtime.h>
#include <cuda_bf16.h>
#include <math.h>

// Problem constants: B=4, S=4096, H=2048, E=8, K=2
#define T_TOKENS 16384
#define HDIM     2048
#define NEXP     8
#define TOPK     2
#define H4       (HDIM / 4)     // 512 float4 per row
#define TPW      8              // tokens per warp
#define NSTAGE   32             // stages per warp; 16 float4 of H per stage
#define DEPTH    4              // smem ring depth
#define WARPS    2              // warps per CTA
#define STAGE_B  (TPW * 256)    // bytes per stage (8 tokens x 256B slice)

// Zero-initialized at module load; last block re-zeros after each use so
// every graph replay sees a clean state (deterministic).
__device__ int g_counts[NEXP];
__device__ unsigned int g_done;

// x is streamed GMEM->SMEM with cp.async.bulk (UBLKCP): no per-16B LDGSTS
// issue cost (the R6 2.6TB/s ceiling) and no registers held by in-flight
// data (the R7/R11 4.4TB/s ceiling). Each warp owns a depth-4 ring of 2KB
// stages; lane 0 re-arms a per-slot mbarrier (expect_tx=2048) and issues 8
// 256B bulk copies (one per token row slice). ~3 stages always in flight.
// Compute structure unchanged from the verified R7 kernel: half-warp expert
// split (lanes 0-15 experts 0-3, lanes 16-31 experts 4-7), w via __ldg (L1).
// 1024 CTAs x 64 threads = 2048 warps = T/8 groups.
__global__ __launch_bounds__(64, 8)
void router_kernel(const float* __restrict__ x,
                   const float* __restrict__ gate_w,
                   float* __restrict__ out) {
    // [warp][slot][tok][16 float4] = 16 KB per CTA
    __shared__ float4 s_x[WARPS][DEPTH][TPW][16];
    __shared__ __align__(8) unsigned long long s_mbar[WARPS][DEPTH];
    __shared__ int s_counts[NEXP];

    const int tid = threadIdx.x;
    if (tid < NEXP) s_counts[tid] = 0;
    if (tid == 0) {
        #pragma unroll
        for (int w = 0; w < WARPS; w++)
            #pragma unroll
            for (int k = 0; k < DEPTH; k++) {
                unsigned mb = (unsigned)__cvta_generic_to_shared(&s_mbar[w][k]);
                asm volatile("mbarrier.init.shared.b64 [%0], %1;"
                             :: "r"(mb), "r"(1) : "memory");
            }
    }
    __syncthreads();

    const int lane        = tid & 31;
    const int wid         = tid >> 5;
    const int l4          = lane & 15;        // position within half-warp
    const int ebase       = (lane >> 4) * 4;  // this half-warp's expert base
    const int warp_global = (blockIdx.x * blockDim.x + tid) >> 5;
    const int t0          = warp_global * TPW;

    const float4* __restrict__ w4 = (const float4*)gate_w;
    const char*   xrow0 = (const char*)(x + (size_t)t0 * HDIM);  // token 0 row

    const unsigned sx_base =
        (unsigned)__cvta_generic_to_shared(&s_x[wid][0][0][0]);
    unsigned mb_addr[DEPTH];
    #pragma unroll
    for (int k = 0; k < DEPTH; k++)
        mb_addr[k] = (unsigned)__cvta_generic_to_shared(&s_mbar[wid][k]);

    // acc[m*4 + j] : token m, local expert j (32 regs)
    float acc[TPW * 4];
    #pragma unroll
    for (int p = 0; p < TPW * 4; p++) acc[p] = 0.0f;

    // Issue one stage: re-arm slot mbarrier, then 8 x 256B bulk copies.
    // Producer == consumer warp, so slot reuse is program-ordered (slot for
    // stage s+3 was last read at stage s-1, one full iteration earlier).
#define ISSUE_STAGE(S)                                                       \
    do {                                                                     \
        if (lane == 0) {                                                     \
            const int _slot = (S) & (DEPTH - 1);                             \
            asm volatile("mbarrier.arrive.expect_tx.shared.b64 _, [%0], %1;" \
                         :: "r"(mb_addr[_slot]), "r"(STAGE_B) : "memory");   \
            const unsigned _dst = sx_base + _slot * (TPW * 256);             \
            const char* _src = xrow0 + 256 * (S);                            \
            _Pragma("unroll")                                                \
            for (int m = 0; m < TPW; m++)                                    \
                asm volatile(                                                \
                    "cp.async.bulk.shared::cta.global"                       \
                    ".mbarrier::complete_tx::bytes [%0], [%1], %2, [%3];"    \
                    :: "r"(_dst + m * 256),                                  \
                       "l"(_src + (size_t)m * (HDIM * 4)),                   \
                       "r"(256), "r"(mb_addr[(S) & (DEPTH - 1)])             \
                    : "memory");                                             \
        }                                                                    \
    } while (0)

    ISSUE_STAGE(0);
    ISSUE_STAGE(1);
    ISSUE_STAGE(2);

    #pragma unroll 4
    for (int s = 0; s < NSTAGE; s++) {
        if (s + 3 < NSTAGE) ISSUE_STAGE(s + 3);

        // Wait for stage s (acquire orders bulk writes before our LDS).
        {
            const unsigned mb = mb_addr[s & (DEPTH - 1)];
            const unsigned parity = (unsigned)((s >> 2) & 1);
            unsigned done;
            asm volatile(
                "{\n\t.reg .pred p;\n\t"
                "mbarrier.try_wait.parity.acquire.cta.shared::cta.b64 p, [%1], %2;\n\t"
                "selp.b32 %0, 1, 0, p;\n\t}"
                : "=r"(done) : "r"(mb), "r"(parity) : "memory");
            if (!done) {
                asm volatile(
                    "{\n\t.reg .pred P1;\n\t"
                    "WL_%=:\n\t"
                    "mbarrier.try_wait.parity.acquire.cta.shared::cta.b64 P1, [%0], %1, 0x989680;\n\t"
                    "@P1 bra.uni WD_%=;\n\t"
                    "bra.uni WL_%=;\n\t"
                    "WD_%=:\n\t}"
                    :: "r"(mb), "r"(parity) : "memory");
            }
        }

        // Consume: lane reads its float4 (position l4) of each token; both
        // half-warps read the same 256B slice -> smem broadcast (free).
        const int slot = s & (DEPTH - 1);
        const int i    = l4 + 16 * s;    // H-position for w
        float4 wv[4];
        #pragma unroll
        for (int j = 0; j < 4; j++)
            wv[j] = __ldg(w4 + (size_t)(ebase + j) * H4 + i);

        #pragma unroll
        for (int m = 0; m < TPW; m++) {
            const float4 xv = s_x[wid][slot][m][l4];
            #pragma unroll
            for (int j = 0; j < 4; j++) {
                acc[m * 4 + j] = fmaf(xv.x, wv[j].x, acc[m * 4 + j]);
                acc[m * 4 + j] = fmaf(xv.y, wv[j].y, acc[m * 4 + j]);
                acc[m * 4 + j] = fmaf(xv.z, wv[j].z, acc[m * 4 + j]);
                acc[m * 4 + j] = fmaf(xv.w, wv[j].w, acc[m * 4 + j]);
            }
        }
    }
#undef ISSUE_STAGE

    // Halving reduction over 32 partials within each 16-lane half-warp
    // (static indices only; offsets <=8 never cross the half-warp).
    // Result: lane l4 holds a[0] = sum(group 2*l4), a[1] = sum(group 2*l4+1),
    // group = tok*4 + local_expert.
    float a[32];
    #pragma unroll
    for (int p = 0; p < 32; p++) a[p] = acc[p];
#define RED_LEVEL(O, L2)                                                   \
    _Pragma("unroll")                                                      \
    for (int j = 0; j < (L2); j++) {                                       \
        float mine  = (lane & (O)) ? a[j + (L2)] : a[j];                   \
        float yours = (lane & (O)) ? a[j] : a[j + (L2)];                   \
        a[j] = mine + __shfl_xor_sync(0xFFFFFFFFu, yours, (O));            \
    }
    RED_LEVEL(8, 16)
    RED_LEVEL(4, 8)
    RED_LEVEL(2, 4)
    RED_LEVEL(1, 2)
#undef RED_LEVEL

    // Lane (hw, l4) holds token l4>>1, experts ebase + 2*(l4&1) + {0,1}.
    // Gather token t's 8 logits: lanes 2t, 2t+1 (experts 0-3) and
    // 16+2t, 17+2t (experts 4-7). Every lane rebuilds its token t = lane>>2.
    const int tok = lane >> 2;
    float l[NEXP];
    l[0] = __shfl_sync(0xFFFFFFFFu, a[0], 2 * tok);
    l[1] = __shfl_sync(0xFFFFFFFFu, a[1], 2 * tok);
    l[2] = __shfl_sync(0xFFFFFFFFu, a[0], 2 * tok + 1);
    l[3] = __shfl_sync(0xFFFFFFFFu, a[1], 2 * tok + 1);
    l[4] = __shfl_sync(0xFFFFFFFFu, a[0], 16 + 2 * tok);
    l[5] = __shfl_sync(0xFFFFFFFFu, a[1], 16 + 2 * tok);
    l[6] = __shfl_sync(0xFFFFFFFFu, a[0], 17 + 2 * tok);
    l[7] = __shfl_sync(0xFFFFFFFFu, a[1], 17 + 2 * tok);

    if ((lane & 3) == 0) {
        const int t = t0 + tok;

        // top-1 (strict > keeps lowest index on tie, matching jax top_k)
        float m1 = l[0]; int i1 = 0;
        #pragma unroll
        for (int e = 1; e < NEXP; e++)
            if (l[e] > m1) { m1 = l[e]; i1 = e; }
        // top-2
        float m2 = -INFINITY; int i2 = 0;
        #pragma unroll
        for (int e = 0; e < NEXP; e++)
            if (e != i1 && l[e] > m2) { m2 = l[e]; i2 = e; }

        // renormalized top-2 softmax weights
        float e2  = __expf(m2 - m1);    // <= 1, numerically safe
        float inv = 1.0f / (1.0f + e2);

        out[(size_t)t * TOPK + 0] = inv;
        out[(size_t)t * TOPK + 1] = e2 * inv;
        out[(size_t)T_TOKENS * TOPK + (size_t)t * TOPK + 0] = (float)i1;
        out[(size_t)T_TOKENS * TOPK + (size_t)t * TOPK + 1] = (float)i2;

        atomicAdd(&s_counts[i1], 1);
        atomicAdd(&s_counts[i2], 1);
    }

    __syncthreads();
    if (tid < NEXP)
        atomicAdd(&g_counts[tid], s_counts[tid]);
    __threadfence();
    __syncthreads();

    // Last block computes the aux loss and resets global state.
    if (tid == 0) {
        unsigned int prev = atomicAdd(&g_done, 1u);
        if (prev == gridDim.x - 1) {
            volatile int* vc = (volatile int*)g_counts;
            float mpe[NEXP];
            float mu = 0.0f;
            #pragma unroll
            for (int e = 0; e < NEXP; e++) {
                mpe[e] = (float)vc[e] / (float)T_TOKENS;
                mu += mpe[e];
            }
            mu *= (1.0f / NEXP);
            float v = 0.0f;
            #pragma unroll
            for (int e = 0; e < NEXP; e++) {
                float d = mpe[e] - mu;
                v += d * d;
            }
            v *= (1.0f / (NEXP - 1));   // unbiased variance (ddof=1)
            out[(size_t)T_TOKENS * TOPK * 2] = v * (float)NEXP;

            // Reset for the next graph replay.
            #pragma unroll
            for (int e = 0; e < NEXP; e++) g_counts[e] = 0;
            g_done = 0u;
        }
    }
}

extern "C" void kernel_launch(void* const* d_in, const int* in_sizes, int n_in,
                              void* d_out, int out_size) {
    const float* x      = (const float*)d_in[0];   // (B,S,H) = (T, H)
    const float* gate_w = (const float*)d_in[1];   // (E, H)
    float* out = (float*)d_out;

    router_kernel<<<1024, 64>>>(x, gate_w, out);
}

// round 13
// speedup vs baseline: 1.4316x; 1.4316x over previous
#include <cuda_runtime.h>
#include <cuda_bf16.h>
#include <math.h>

// Problem constants: B=4, S=4096, H=2048, E=8, K=2
#define T_TOKENS 16384
#define HDIM     2048
#define NEXP     8
#define TOPK     2
#define H4       (HDIM / 4)   // 512 float4 per row
#define TPW      8            // tokens per warp
#define NITER    (H4 / 16)    // 32: each half-warp covers 16 float4 per iter
#define PFDIST   3            // extra L2-prefetch distance beyond reg prefetch

// Zero-initialized at module load; last block re-zeros after each use so
// every graph replay sees a clean state (deterministic).
__device__ int g_counts[NEXP];
__device__ unsigned int g_done;

// One warp = 8 tokens. Half-warp expert split: lanes 0-15 own experts 0-3,
// lanes 16-31 own experts 4-7. x uses a register double-buffer prefetch
// (distance 1) PLUS zero-register L2 prefetches 3 iterations further ahead:
// the DRAM->L2 fetch stream is driven by prefetch issue rate instead of the
// ~35%-duty LDG batch cycle, and the blocking LDG becomes an L2 hit.
// 1024 CTAs x 64 threads = 2048 warps = T/8 groups, single balanced wave.
__global__ __launch_bounds__(64, 8)
void router_kernel(const float* __restrict__ x,
                   const float* __restrict__ gate_w,
                   float* __restrict__ out) {
    __shared__ int s_counts[NEXP];
    if (threadIdx.x < NEXP) s_counts[threadIdx.x] = 0;
    __syncthreads();

    const int lane        = threadIdx.x & 31;
    const int l4          = lane & 15;        // position within half-warp
    const int ebase       = (lane >> 4) * 4;  // this half-warp's expert base
    const int warp_global = (blockIdx.x * blockDim.x + threadIdx.x) >> 5;
    const int t0          = warp_global * TPW;

    const float4* __restrict__ x4 = (const float4*)x;
    const float4* __restrict__ w4 = (const float4*)gate_w;
    const float4* __restrict__ xb0 = x4 + (size_t)t0 * H4 + l4;  // token 0, iter 0

    // acc[m*4 + j] : token m, local expert j (32 regs)
    float acc[TPW * 4];
    #pragma unroll
    for (int p = 0; p < TPW * 4; p++) acc[p] = 0.0f;

    float4 xa[TPW], xb[TPW];

    // Prologue: load iteration 0's x into buffer A, and L2-prefetch the next
    // few iterations so the DRAM stream starts deep.
    #pragma unroll
    for (int m = 0; m < TPW; m++) {
        const float4* p = xb0 + (size_t)m * H4;
        xa[m] = __ldg(p);
        asm volatile("prefetch.global.L2 [%0];" :: "l"((const char*)p + 256));
        asm volatile("prefetch.global.L2 [%0];" :: "l"((const char*)p + 512));
        asm volatile("prefetch.global.L2 [%0];" :: "l"((const char*)p + 768));
    }

    // One step: reg-prefetch x for (IT+1) into NXT, L2-prefetch (IT+1+PFDIST),
    // compute iteration IT from CUR.
#define STEP(CUR, NXT, IT)                                                   \
    do {                                                                     \
        const int _nit = (IT) + 1;                                           \
        if (_nit < NITER) {                                                  \
            _Pragma("unroll")                                                \
            for (int m = 0; m < TPW; m++) {                                  \
                const float4* _p = xb0 + (size_t)m * H4 + 16 * _nit;         \
                NXT[m] = __ldg(_p);                                          \
                if (_nit + PFDIST < NITER)                                   \
                    asm volatile("prefetch.global.L2 [%0];"                  \
                                 :: "l"((const char*)_p + 256 * PFDIST));    \
            }                                                                \
        }                                                                    \
        const int _i = l4 + 16 * (IT);                                       \
        float4 wv[4];                                                        \
        _Pragma("unroll")                                                    \
        for (int j = 0; j < 4; j++)                                          \
            wv[j] = __ldg(w4 + (size_t)(ebase + j) * H4 + _i);               \
        _Pragma("unroll")                                                    \
        for (int j = 0; j < 4; j++)                                          \
            _Pragma("unroll")                                                \
            for (int m = 0; m < TPW; m++) {                                  \
                acc[m * 4 + j] = fmaf(CUR[m].x, wv[j].x, acc[m * 4 + j]);    \
                acc[m * 4 + j] = fmaf(CUR[m].y, wv[j].y, acc[m * 4 + j]);    \
                acc[m * 4 + j] = fmaf(CUR[m].z, wv[j].z, acc[m * 4 + j]);    \
                acc[m * 4 + j] = fmaf(CUR[m].w, wv[j].w, acc[m * 4 + j]);    \
            }                                                                \
    } while (0)

    #pragma unroll 1
    for (int it2 = 0; it2 < NITER / 2; it2++) {
        STEP(xa, xb, 2 * it2);
        STEP(xb, xa, 2 * it2 + 1);
    }
#undef STEP

    // Halving reduction over 32 partials within each 16-lane half-warp
    // (static indices only; offsets <=8 never cross the half-warp).
    // Result: lane l4 holds a[0] = sum(group 2*l4), a[1] = sum(group 2*l4+1),
    // group = tok*4 + local_expert.
    float a[32];
    #pragma unroll
    for (int p = 0; p < 32; p++) a[p] = acc[p];
#define RED_LEVEL(O, L2)                                                   \
    _Pragma("unroll")                                                      \
    for (int j = 0; j < (L2); j++) {                                       \
        float mine  = (lane & (O)) ? a[j + (L2)] : a[j];                   \
        float yours = (lane & (O)) ? a[j] : a[j + (L2)];                   \
        a[j] = mine + __shfl_xor_sync(0xFFFFFFFFu, yours, (O));            \
    }
    RED_LEVEL(8, 16)
    RED_LEVEL(4, 8)
    RED_LEVEL(2, 4)
    RED_LEVEL(1, 2)
#undef RED_LEVEL

    // Lane (hw, l4) holds token l4>>1, experts ebase + 2*(l4&1) + {0,1}.
    // Gather token t's 8 logits: lanes 2t, 2t+1 (experts 0-3) and
    // 16+2t, 17+2t (experts 4-7). Every lane rebuilds its token t = lane>>2.
    const int tok = lane >> 2;
    float l[NEXP];
    l[0] = __shfl_sync(0xFFFFFFFFu, a[0], 2 * tok);
    l[1] = __shfl_sync(0xFFFFFFFFu, a[1], 2 * tok);
    l[2] = __shfl_sync(0xFFFFFFFFu, a[0], 2 * tok + 1);
    l[3] = __shfl_sync(0xFFFFFFFFu, a[1], 2 * tok + 1);
    l[4] = __shfl_sync(0xFFFFFFFFu, a[0], 16 + 2 * tok);
    l[5] = __shfl_sync(0xFFFFFFFFu, a[1], 16 + 2 * tok);
    l[6] = __shfl_sync(0xFFFFFFFFu, a[0], 17 + 2 * tok);
    l[7] = __shfl_sync(0xFFFFFFFFu, a[1], 17 + 2 * tok);

    if ((lane & 3) == 0) {
        const int t = t0 + tok;

        // top-1 (strict > keeps lowest index on tie, matching jax top_k)
        float m1 = l[0]; int i1 = 0;
        #pragma unroll
        for (int e = 1; e < NEXP; e++)
            if (l[e] > m1) { m1 = l[e]; i1 = e; }
        // top-2
        float m2 = -INFINITY; int i2 = 0;
        #pragma unroll
        for (int e = 0; e < NEXP; e++)
            if (e != i1 && l[e] > m2) { m2 = l[e]; i2 = e; }

        // renormalized top-2 softmax weights
        float e2  = __expf(m2 - m1);    // <= 1, numerically safe
        float inv = 1.0f / (1.0f + e2);

        out[(size_t)t * TOPK + 0] = inv;
        out[(size_t)t * TOPK + 1] = e2 * inv;
        out[(size_t)T_TOKENS * TOPK + (size_t)t * TOPK + 0] = (float)i1;
        out[(size_t)T_TOKENS * TOPK + (size_t)t * TOPK + 1] = (float)i2;

        atomicAdd(&s_counts[i1], 1);
        atomicAdd(&s_counts[i2], 1);
    }

    __syncthreads();
    if (threadIdx.x < NEXP)
        atomicAdd(&g_counts[threadIdx.x], s_counts[threadIdx.x]);
    __threadfence();
    __syncthreads();

    // Last block computes the aux loss and resets global state.
    if (threadIdx.x == 0) {
        unsigned int prev = atomicAdd(&g_done, 1u);
        if (prev == gridDim.x - 1) {
            volatile int* vc = (volatile int*)g_counts;
            float mpe[NEXP];
            float mu = 0.0f;
            #pragma unroll
            for (int e = 0; e < NEXP; e++) {
                mpe[e] = (float)vc[e] / (float)T_TOKENS;
                mu += mpe[e];
            }
            mu *= (1.0f / NEXP);
            float v = 0.0f;
            #pragma unroll
            for (int e = 0; e < NEXP; e++) {
                float d = mpe[e] - mu;
                v += d * d;
            }
            v *= (1.0f / (NEXP - 1));   // unbiased variance (ddof=1)
            out[(size_t)T_TOKENS * TOPK * 2] = v * (float)NEXP;

            // Reset for the next graph replay.
            #pragma unroll
            for (int e = 0; e < NEXP; e++) g_counts[e] = 0;
            g_done = 0u;
        }
    }
}

extern "C" void kernel_launch(void* const* d_in, const int* in_sizes, int n_in,
                              void* d_out, int out_size) {
    const float* x      = (const float*)d_in[0];   // (B,S,H) = (T, H)
    const float* gate_w = (const float*)d_in[1];   // (E, H)
    float* out = (float*)d_out;

    router_kernel<<<1024, 64>>>(x, gate_w, out);
}